// round 10
// baseline (speedup 1.0000x reference)
#include <cuda_runtime.h>
#include <cuda_bf16.h>

// Problem constants: N=2,000,000 rows, P=64 features, C=100 classes.
#define PFEAT     64
#define NCLASS    100
#define NWARPS    16                  // class ownership = cls & 15
#define THREADS1  (NWARPS * 32)
#define GRID1     444                 // 148 SMs * 3 resident CTAs (62.5KB smem each)
#define RBINS     (NCLASS * 16)       // per-replica float4 s-bins: [class][l16]
#define SMEM1     (2 * RBINS * 16 + 2 * RBINS * 4)   // 64,000 B

// Deterministic scratch (fixed-order reduction; no float atomics anywhere).
__device__ float4 g_s  [(size_t)GRID1 * 2 * RBINS];  // ~22.7 MB [cta][rep][class][l16]
__device__ float  g_ss [(size_t)GRID1 * 2 * RBINS];  // ~5.7 MB
__device__ float  g_cnt[GRID1 * NCLASS];
__device__ double g_class[NCLASS];

// ---------------------------------------------------------------------------
// Kernel 1: warp w owns classes with (cls & 15) == w  ->  no inter-warp races.
// Two rows per warp-op: lanes 0-15 (replica 0) process row b0, lanes 16-31
// (replica 1) process row b1. Replicated bins make same-class pairs safe.
// One LDG.128 + one LDS.128-RMW + one per-lane-source SHFL covers both rows.
// ---------------------------------------------------------------------------
__global__ __launch_bounds__(THREADS1, 3)
void k1_accumulate(const float4* __restrict__ x4,
                   const int* __restrict__ t, int N)   // t is int32
{
    extern __shared__ unsigned char dyn[];
    float4* s_acc  = reinterpret_cast<float4*>(dyn);                 // [2][NCLASS][16]
    float*  ss_acc = reinterpret_cast<float*>(dyn + 2 * RBINS * 16); // [2][NCLASS][16]

    const int  tid  = threadIdx.x;
    const int  w    = tid >> 5;
    const int  lane = tid & 31;
    const int  l16  = lane & 15;
    const int  rep  = lane >> 4;       // 0 = lo half, 1 = hi half

    for (int i = tid; i < 2 * RBINS; i += THREADS1) {
        s_acc[i]  = make_float4(0.f, 0.f, 0.f, 0.f);
        ss_acc[i] = 0.f;
    }
    __syncthreads();

    const int chunk = (N + GRID1 - 1) / GRID1;
    const int beg   = blockIdx.x * chunk;
    const int end   = min(N, beg + chunk);

    float rc = 0.f;   // per-half register count: l16 == (cls>>4) counts that class

    for (int base = beg; base < end; base += 32) {
        int r   = base + lane;
        int cls = (r < end) ? t[r] : -1;
        bool own = (cls >= 0) && (cls < NCLASS) && ((cls & (NWARPS - 1)) == w);
        unsigned m = __ballot_sync(0xffffffffu, own);

        while (m) {
            int b0 = __ffs(m) - 1;  m &= m - 1;
            int b1 = -1;
            if (m) { b1 = __ffs(m) - 1; m &= m - 1; }

            // lo half fetches row b0's class, hi half row b1's (one SHFL).
            int src = rep ? (b1 & 31) : b0;
            int myc = __shfl_sync(0xffffffffu, cls, src);
            int myb = rep ? b1 : b0;

            if (myb >= 0) {
                // 16 lanes x 16B = one 256B row per half; one LDG.128 = 2 rows.
                float4 v = x4[(size_t)(base + myb) * (PFEAT / 4) + l16];
                int idx = rep * RBINS + myc * 16 + l16;     // replica-private bin
                float4 a = s_acc[idx];
                a.x += v.x; a.y += v.y; a.z += v.z; a.w += v.w;
                s_acc[idx] = a;
                ss_acc[idx] += v.x * v.x + v.y * v.y + v.z * v.z + v.w * v.w;
                if (l16 == (myc >> 4)) rc += 1.f;
            }
        }
    }
    __syncthreads();

    const size_t off = (size_t)blockIdx.x * (2 * RBINS);
    for (int i = tid; i < 2 * RBINS; i += THREADS1) {
        g_s [off + i] = s_acc[i];
        g_ss[off + i] = ss_acc[i];
    }
    // counts: class w + 16*l  =  rc(lane=l) + rc(lane=16+l)
    float rcHi = __shfl_down_sync(0xffffffffu, rc, 16);
    int c = w + 16 * lane;
    if (lane < 7 && c < NCLASS)
        g_cnt[blockIdx.x * NCLASS + c] = rc + rcHi;
}

// ---------------------------------------------------------------------------
// Kernel 2: one CTA (256 thr) per class; fixed-order reduction of partials.
// Lanes 0-15 reduce replica 0, lanes 16-31 replica 1; replicas are summed
// BEFORE squaring (same features live in both replicas).
// ---------------------------------------------------------------------------
__global__ __launch_bounds__(256)
void k2_per_class()
{
    const int c    = blockIdx.x;
    const int tid  = threadIdx.x;
    const int w    = tid >> 5;
    const int lane = tid & 31;
    const int l16  = lane & 15;
    const int rep  = lane >> 4;

    __shared__ float4 sa[256];
    __shared__ float  sb[256];
    __shared__ float  sc[256];

    float4 a   = make_float4(0.f, 0.f, 0.f, 0.f);
    float  ssp = 0.f;
    for (int b = w; b < GRID1; b += 8) {
        size_t base = (size_t)b * (2 * RBINS) + rep * RBINS + c * 16 + l16;
        float4 p = g_s[base];
        a.x += p.x; a.y += p.y; a.z += p.z; a.w += p.w;
        ssp += g_ss[base];
    }
    sa[tid] = a;
    sb[tid] = ssp;

    float cn = 0.f;
    for (int b = tid; b < GRID1; b += 256) cn += g_cnt[b * NCLASS + c];
    sc[tid] = cn;
    __syncthreads();

    if (tid < 32) {
        float4 tot = sa[lane];
        float  ss  = sb[lane];
        float  n   = sc[lane];
        #pragma unroll
        for (int j = 1; j < 8; j++) {
            float4 p = sa[j * 32 + lane];
            tot.x += p.x; tot.y += p.y; tot.z += p.z; tot.w += p.w;
            ss += sb[j * 32 + lane];
            n  += sc[j * 32 + lane];
        }
        #pragma unroll
        for (int o = 16; o > 0; o >>= 1) n += __shfl_xor_sync(0xffffffffu, n, o);

        // Combine replicas per feature, then square (in double).
        float hx = __shfl_down_sync(0xffffffffu, tot.x, 16);
        float hy = __shfl_down_sync(0xffffffffu, tot.y, 16);
        float hz = __shfl_down_sync(0xffffffffu, tot.z, 16);
        float hw = __shfl_down_sync(0xffffffffu, tot.w, 16);

        double dA = 0.0;
        if (lane < 16) {
            double sx = (double)tot.x + (double)hx;
            double sy = (double)tot.y + (double)hy;
            double sz = (double)tot.z + (double)hz;
            double sw = (double)tot.w + (double)hw;
            dA = sx * sx + sy * sy + sz * sz + sw * sw;
        }
        double dB = (double)ss;
        #pragma unroll
        for (int o = 16; o > 0; o >>= 1) {
            dA += __shfl_xor_sync(0xffffffffu, dA, o);
            dB += __shfl_xor_sync(0xffffffffu, dB, o);
        }

        double dn = (double)n;
        double contrib = (dB - dA / dn) / (dn - 1.0);
        if (lane == 0) g_class[c] = contrib;
    }
}

// ---------------------------------------------------------------------------
// Kernel 3: final deterministic reduction of the 100 class scalars.
// ---------------------------------------------------------------------------
__global__ void k3_final(float* __restrict__ out)
{
    if (threadIdx.x == 0) {
        double total = 0.0;
        for (int c = 0; c < NCLASS; c++) total += g_class[c];
        out[0] = (float)(total / (double)NCLASS);
    }
}

extern "C" void kernel_launch(void* const* d_in, const int* in_sizes, int n_in,
                              void* d_out, int out_size)
{
    const float4* x4  = (const float4*)d_in[0];
    const int*    t   = (const int*)d_in[1];          // int32 labels
    float*        out = (float*)d_out;
    const int N = in_sizes[0] / PFEAT;

    // Opt-in to >48KB dynamic shared memory (unconditional each call).
    cudaFuncSetAttribute(k1_accumulate, cudaFuncAttributeMaxDynamicSharedMemorySize, SMEM1);

    k1_accumulate<<<GRID1, THREADS1, SMEM1>>>(x4, t, N);
    k2_per_class<<<NCLASS, 256>>>();
    k3_final<<<1, 32>>>(out);
}

// round 12
// speedup vs baseline: 1.0331x; 1.0331x over previous
#include <cuda_runtime.h>
#include <cuda_bf16.h>

// Problem constants: N=2,000,000 rows, P=64 features, C=100 classes.
#define PFEAT     64
#define NCLASS    100
#define NWARPS    16                  // class ownership = cls & 15
#define THREADS1  (NWARPS * 32)
#define GRID1     444                 // 148 SMs * 3 resident CTAs (reg-limited occ 75%)
#define BINS      (NCLASS * 32)       // [class][lane] bins

// Deterministic scratch (fixed-order reduction; no float atomics anywhere).
__device__ float2 g_s  [(size_t)GRID1 * BINS];   // ~11.4 MB per-CTA per-(class,featpair) sums
__device__ float  g_ss [(size_t)GRID1 * BINS];   // ~5.7 MB  per-CTA per-(class,lane) ss partials
__device__ float  g_cnt[GRID1 * NCLASS];
__device__ double g_class[NCLASS];

// ---------------------------------------------------------------------------
// Kernel 1: warp w owns classes with (cls & 15) == w -> no atomics, no races
// (each lane only ever RMWs bin column [*, lane]).
// 64-row ballot window (64-bit mask) + 4-wide extraction: four independent
// 256B x-row loads are in flight before any RMW, so one DRAM round-trip
// covers ~4 owned rows instead of 2 -> shorter per-warp serial chain.
// ---------------------------------------------------------------------------
__global__ __launch_bounds__(THREADS1, 3)
void k1_accumulate(const float2* __restrict__ x2,
                   const int* __restrict__ t, int N)   // t is int32
{
    __shared__ float2 s_acc [BINS];   // 25.6 KB
    __shared__ float  ss_acc[BINS];   // 12.8 KB

    const int tid  = threadIdx.x;
    const int w    = tid >> 5;
    const int lane = tid & 31;

    for (int i = tid; i < BINS; i += THREADS1) {
        s_acc[i]  = make_float2(0.f, 0.f);
        ss_acc[i] = 0.f;
    }
    __syncthreads();

    const int chunk = (N + GRID1 - 1) / GRID1;
    const int beg   = blockIdx.x * chunk;
    const int end   = min(N, beg + chunk);

    float rc = 0.f;   // register count: lane k counts class w + 16*k

    for (int base = beg; base < end; base += 64) {
        int ra = base + lane;
        int rb = base + 32 + lane;
        int cls_a = (ra < end) ? t[ra] : -1;
        int cls_b = (rb < end) ? t[rb] : -1;
        bool own_a = (cls_a >= 0) && (cls_a < NCLASS) && ((cls_a & (NWARPS - 1)) == w);
        bool own_b = (cls_b >= 0) && (cls_b < NCLASS) && ((cls_b & (NWARPS - 1)) == w);
        unsigned mlo = __ballot_sync(0xffffffffu, own_a);
        unsigned mhi = __ballot_sync(0xffffffffu, own_b);
        unsigned long long m = (unsigned long long)mlo |
                               ((unsigned long long)mhi << 32);

        while (m) {
            // Extract up to 4 owned rows (uniform), THEN issue all loads.
            int b0 = __ffsll(m) - 1;  m &= m - 1;
            int b1 = -1, b2 = -1, b3 = -1;
            if (m) { b1 = __ffsll(m) - 1; m &= m - 1; }
            if (m) { b2 = __ffsll(m) - 1; m &= m - 1; }
            if (m) { b3 = __ffsll(m) - 1; m &= m - 1; }

            // class of bit b: lane b&31 of cls_a (b<32) or cls_b (b>=32)
            int a0 = __shfl_sync(0xffffffffu, cls_a, b0 & 31);
            int q0 = __shfl_sync(0xffffffffu, cls_b, b0 & 31);
            int a1 = __shfl_sync(0xffffffffu, cls_a, b1 & 31);
            int q1 = __shfl_sync(0xffffffffu, cls_b, b1 & 31);
            int a2 = __shfl_sync(0xffffffffu, cls_a, b2 & 31);
            int q2 = __shfl_sync(0xffffffffu, cls_b, b2 & 31);
            int a3 = __shfl_sync(0xffffffffu, cls_a, b3 & 31);
            int q3 = __shfl_sync(0xffffffffu, cls_b, b3 & 31);
            int c0 = (b0 & 32) ? q0 : a0;
            int c1 = (b1 & 32) ? q1 : a1;
            int c2 = (b2 & 32) ? q2 : a2;
            int c3 = (b3 & 32) ? q3 : a3;

            // 4 independent 256B coalesced row loads (lane -> feats 2*lane,2*lane+1)
            float2 v0, v1, v2, v3;
            v0 = x2[(size_t)(base + b0) * (PFEAT / 2) + lane];
            if (b1 >= 0) v1 = x2[(size_t)(base + b1) * (PFEAT / 2) + lane];
            if (b2 >= 0) v2 = x2[(size_t)(base + b2) * (PFEAT / 2) + lane];
            if (b3 >= 0) v3 = x2[(size_t)(base + b3) * (PFEAT / 2) + lane];

            {   // row b0 (always valid)
                int idx = c0 * 32 + lane;
                float2 a = s_acc[idx];
                a.x += v0.x; a.y += v0.y;
                s_acc[idx] = a;
                ss_acc[idx] += v0.x * v0.x + v0.y * v0.y;
                if (lane == (c0 >> 4)) rc += 1.f;
            }
            if (b1 >= 0) {
                int idx = c1 * 32 + lane;
                float2 a = s_acc[idx];
                a.x += v1.x; a.y += v1.y;
                s_acc[idx] = a;
                ss_acc[idx] += v1.x * v1.x + v1.y * v1.y;
                if (lane == (c1 >> 4)) rc += 1.f;
            }
            if (b2 >= 0) {
                int idx = c2 * 32 + lane;
                float2 a = s_acc[idx];
                a.x += v2.x; a.y += v2.y;
                s_acc[idx] = a;
                ss_acc[idx] += v2.x * v2.x + v2.y * v2.y;
                if (lane == (c2 >> 4)) rc += 1.f;
            }
            if (b3 >= 0) {
                int idx = c3 * 32 + lane;
                float2 a = s_acc[idx];
                a.x += v3.x; a.y += v3.y;
                s_acc[idx] = a;
                ss_acc[idx] += v3.x * v3.x + v3.y * v3.y;
                if (lane == (c3 >> 4)) rc += 1.f;
            }
        }
    }
    __syncthreads();

    const size_t off = (size_t)blockIdx.x * BINS;
    for (int i = tid; i < BINS; i += THREADS1) {
        g_s [off + i] = s_acc[i];
        g_ss[off + i] = ss_acc[i];
    }
    // counts: warp w holds class w + 16*lane in rc (lane < 7)
    int c = w + 16 * lane;
    if (lane < 7 && c < NCLASS)
        g_cnt[blockIdx.x * NCLASS + c] = rc;
}

// ---------------------------------------------------------------------------
// Kernel 2: one CTA (256 thr) per class; fixed-order reduction of partials.
// ---------------------------------------------------------------------------
__global__ __launch_bounds__(256)
void k2_per_class()
{
    const int c    = blockIdx.x;
    const int tid  = threadIdx.x;
    const int w    = tid >> 5;
    const int lane = tid & 31;

    __shared__ float2 sa[256];
    __shared__ float  sb[256];
    __shared__ float  sc[256];

    float2 a   = make_float2(0.f, 0.f);
    float  ssp = 0.f;
    for (int b = w; b < GRID1; b += 8) {           // coalesced 256B + 128B per (b,warp)
        size_t base = (size_t)b * BINS + c * 32 + lane;
        float2 p = g_s[base];
        a.x += p.x; a.y += p.y;
        ssp += g_ss[base];
    }
    sa[tid] = a;
    sb[tid] = ssp;

    float cn = 0.f;
    for (int b = tid; b < GRID1; b += 256) cn += g_cnt[b * NCLASS + c];
    sc[tid] = cn;
    __syncthreads();

    if (tid < 32) {
        float2 tot = sa[lane];
        float  ss  = sb[lane];
        float  n   = sc[lane];
        #pragma unroll
        for (int j = 1; j < 8; j++) {
            float2 p = sa[j * 32 + lane];
            tot.x += p.x; tot.y += p.y;
            ss += sb[j * 32 + lane];
            n  += sc[j * 32 + lane];
        }
        #pragma unroll
        for (int o = 16; o > 0; o >>= 1) n += __shfl_xor_sync(0xffffffffu, n, o);

        // dA = sum over features of s^2 ; dB = total SS for the class
        double dA = (double)tot.x * tot.x + (double)tot.y * tot.y;
        double dB = (double)ss;
        #pragma unroll
        for (int o = 16; o > 0; o >>= 1) {
            dA += __shfl_xor_sync(0xffffffffu, dA, o);
            dB += __shfl_xor_sync(0xffffffffu, dB, o);
        }

        double dn = (double)n;
        double contrib = (dB - dA / dn) / (dn - 1.0);
        if (lane == 0) g_class[c] = contrib;
    }
}

// ---------------------------------------------------------------------------
// Kernel 3: final deterministic reduction of the 100 class scalars.
// ---------------------------------------------------------------------------
__global__ void k3_final(float* __restrict__ out)
{
    if (threadIdx.x == 0) {
        double total = 0.0;
        for (int c = 0; c < NCLASS; c++) total += g_class[c];
        out[0] = (float)(total / (double)NCLASS);
    }
}

extern "C" void kernel_launch(void* const* d_in, const int* in_sizes, int n_in,
                              void* d_out, int out_size)
{
    const float2* x2  = (const float2*)d_in[0];
    const int*    t   = (const int*)d_in[1];          // int32 labels
    float*        out = (float*)d_out;
    const int N = in_sizes[0] / PFEAT;

    k1_accumulate<<<GRID1, THREADS1>>>(x2, t, N);
    k2_per_class<<<NCLASS, 256>>>();
    k3_final<<<1, 32>>>(out);
}

// round 13
// speedup vs baseline: 1.2587x; 1.2184x over previous
#include <cuda_runtime.h>
#include <cuda_bf16.h>

// Problem constants: N=2,000,000 rows, P=64 features, C=100 classes.
#define PFEAT     64
#define NCLASS    100
#define NWARPS    16                  // class ownership = cls & 15
#define THREADS1  (NWARPS * 32)
#define GRID1     592                 // 148 SMs * 4 resident CTAs
#define BINS      (NCLASS * 32)       // [class][lane] float4 bins {sx, sy, ss, n}
#define SMEM1     (BINS * 16)         // 51,200 B -> dynamic smem (opt-in)

// Deterministic scratch (fixed-order reduction; no float atomics anywhere).
__device__ float4 g_part[(size_t)GRID1 * BINS];   // ~30.3 MB
__device__ double g_class[NCLASS];

// ---------------------------------------------------------------------------
// Kernel 1: warp w owns classes with (cls & 15) == w -> no atomics, and each
// lane only ever RMWs bin column [*, lane] -> no intra-warp aliasing.
// Unified float4 bin {sx, sy, ss, n}: ONE LDS.128/STS.128 RMW per row covers
// the feature-pair sums, the ss scalar, AND the count (every lane adds 1, so
// each lane's .w independently equals n_c).
// ---------------------------------------------------------------------------
__global__ __launch_bounds__(THREADS1, 4)
void k1_accumulate(const float2* __restrict__ x2,
                   const int* __restrict__ t, int N)   // t is int32
{
    extern __shared__ float4 bins[];   // [NCLASS][32]

    const int tid  = threadIdx.x;
    const int w    = tid >> 5;
    const int lane = tid & 31;

    for (int i = tid; i < BINS; i += THREADS1)
        bins[i] = make_float4(0.f, 0.f, 0.f, 0.f);
    __syncthreads();

    const int chunk = (N + GRID1 - 1) / GRID1;
    const int beg   = blockIdx.x * chunk;
    const int end   = min(N, beg + chunk);

    for (int base = beg; base < end; base += 32) {
        int r   = base + lane;
        int cls = (r < end) ? t[r] : -1;
        bool own = (cls >= 0) && (cls < NCLASS) && ((cls & (NWARPS - 1)) == w);
        unsigned m = __ballot_sync(0xffffffffu, own);

        while (m) {
            // Extract up to 2 owned rows, THEN issue both 256B loads (MLP=2).
            int b0 = __ffs(m) - 1;  m &= m - 1;
            int b1 = -1;
            if (m) { b1 = __ffs(m) - 1; m &= m - 1; }

            int c0 = __shfl_sync(0xffffffffu, cls, b0);
            int c1 = __shfl_sync(0xffffffffu, cls, b1 & 31);

            float2 v0, v1;
            v0 = x2[(size_t)(base + b0) * (PFEAT / 2) + lane];
            if (b1 >= 0) v1 = x2[(size_t)(base + b1) * (PFEAT / 2) + lane];

            {   // row b0 (always valid): single 16B RMW does s, ss, n
                int idx = c0 * 32 + lane;
                float4 a = bins[idx];
                a.x += v0.x;
                a.y += v0.y;
                a.z += v0.x * v0.x + v0.y * v0.y;
                a.w += 1.f;
                bins[idx] = a;
            }
            if (b1 >= 0) {
                int idx = c1 * 32 + lane;
                float4 a = bins[idx];
                a.x += v1.x;
                a.y += v1.y;
                a.z += v1.x * v1.x + v1.y * v1.y;
                a.w += 1.f;
                bins[idx] = a;
            }
        }
    }
    __syncthreads();

    const size_t off = (size_t)blockIdx.x * BINS;
    for (int i = tid; i < BINS; i += THREADS1)
        g_part[off + i] = bins[i];
}

// ---------------------------------------------------------------------------
// Kernel 2: one CTA (256 thr) per class; fixed-order reduction of partials.
// After summing across CTAs, each lane's .w equals n_c (uniform, no reduce).
// ---------------------------------------------------------------------------
__global__ __launch_bounds__(256)
void k2_per_class()
{
    const int c    = blockIdx.x;
    const int tid  = threadIdx.x;
    const int w    = tid >> 5;
    const int lane = tid & 31;

    __shared__ float4 sa[256];

    float4 a = make_float4(0.f, 0.f, 0.f, 0.f);
    for (int b = w; b < GRID1; b += 8) {           // 512B coalesced per (b,warp)
        float4 p = g_part[(size_t)b * BINS + c * 32 + lane];
        a.x += p.x; a.y += p.y; a.z += p.z; a.w += p.w;
    }
    sa[tid] = a;
    __syncthreads();

    if (tid < 32) {
        float4 tot = sa[lane];
        #pragma unroll
        for (int j = 1; j < 8; j++) {
            float4 p = sa[j * 32 + lane];
            tot.x += p.x; tot.y += p.y; tot.z += p.z; tot.w += p.w;
        }
        // tot.w is n_c on every lane (each lane counted every row independently).
        double dA = (double)tot.x * tot.x + (double)tot.y * tot.y;  // s^2 partial
        double dB = (double)tot.z;                                   // ss partial
        #pragma unroll
        for (int o = 16; o > 0; o >>= 1) {
            dA += __shfl_xor_sync(0xffffffffu, dA, o);
            dB += __shfl_xor_sync(0xffffffffu, dB, o);
        }
        double dn = (double)tot.w;
        double contrib = (dB - dA / dn) / (dn - 1.0);
        if (lane == 0) g_class[c] = contrib;
    }
}

// ---------------------------------------------------------------------------
// Kernel 3: final deterministic reduction of the 100 class scalars.
// ---------------------------------------------------------------------------
__global__ void k3_final(float* __restrict__ out)
{
    if (threadIdx.x == 0) {
        double total = 0.0;
        for (int c = 0; c < NCLASS; c++) total += g_class[c];
        out[0] = (float)(total / (double)NCLASS);
    }
}

extern "C" void kernel_launch(void* const* d_in, const int* in_sizes, int n_in,
                              void* d_out, int out_size)
{
    const float2* x2  = (const float2*)d_in[0];
    const int*    t   = (const int*)d_in[1];          // int32 labels
    float*        out = (float*)d_out;
    const int N = in_sizes[0] / PFEAT;

    // Opt-in to >48KB dynamic shared memory (unconditional each call).
    cudaFuncSetAttribute(k1_accumulate, cudaFuncAttributeMaxDynamicSharedMemorySize, SMEM1);

    k1_accumulate<<<GRID1, THREADS1, SMEM1>>>(x2, t, N);
    k2_per_class<<<NCLASS, 256>>>();
    k3_final<<<1, 32>>>(out);
}